// round 1
// baseline (speedup 1.0000x reference)
#include <cuda_runtime.h>
#include <cuda_bf16.h>
#include <cstdint>
#include <cstddef>

// Problem constants
#define T_STEPS 1024
#define BATCH   64
#define DIM     512
#define HID     512
#define DH      1024          // D + H
#define G4      2048          // 4*H

// Phase-2 partitioning
#define NGROUPS 4
#define CPG     32            // CTAs per group
#define NCTA    128
#define BPG     16            // batches per group
#define JPC     16            // hidden units per CTA
#define RPC     64            // weight rows per CTA (4 gates * JPC)
#define KP      516           // padded smem row stride (floats)

// ---------------- device scratch (static allocations only) ----------------
__device__ float    g_zx[(size_t)T_STEPS * BATCH * G4];   // 512 MB precomputed x-part + bias
__device__ float    g_h[2][BATCH][HID];                   // double-buffered hidden state
__device__ unsigned g_cnt[NGROUPS];                       // per-group barrier counters

__device__ __forceinline__ unsigned ld_acq(unsigned* p) {
    unsigned v;
    asm volatile("ld.acquire.gpu.u32 %0, [%1];" : "=r"(v) : "l"(p) : "memory");
    return v;
}

// =======================================================================
// Phase 1: Zx[t*B+b, gate*512+j] = x[t,b,:] . W_gate[j, 0:512] + b_gate[j]
// Plain fp32 SGEMM, M=65536, N=2048, K=512. Tile 128x64, 256 threads.
// =======================================================================
__global__ __launch_bounds__(256) void p1_gemm(
    const float* __restrict__ X,
    const float* __restrict__ Wf, const float* __restrict__ Wi,
    const float* __restrict__ Wg, const float* __restrict__ Wo,
    const float* __restrict__ bf, const float* __restrict__ bi,
    const float* __restrict__ bg, const float* __restrict__ bo)
{
    __shared__ float As[16][132];
    __shared__ float Bs[16][68];

    const int tid = threadIdx.x;
    const int m0  = blockIdx.y * 128;
    const int n0  = blockIdx.x * 64;
    const int gate = n0 >> 9;                    // 64 | 512, so tile is gate-pure
    const float* Wsel = (gate == 0) ? Wf : (gate == 1) ? Wi : (gate == 2) ? Wg : Wo;
    const float* bsel = (gate == 0) ? bf : (gate == 1) ? bi : (gate == 2) ? bg : bo;
    const int jbase = n0 - gate * 512;

    const int tm = tid & 15;
    const int tn = tid >> 4;

    float acc[8][4];
#pragma unroll
    for (int i = 0; i < 8; i++)
#pragma unroll
        for (int q = 0; q < 4; q++) acc[i][q] = 0.f;

    for (int k0 = 0; k0 < 512; k0 += 16) {
        // A tile: 128 rows x 16 k  (512 float4, 2 per thread)
#pragma unroll
        for (int l = 0; l < 2; l++) {
            int lin = tid + l * 256;
            int row = lin >> 2, kc = lin & 3;
            float4 v = *(const float4*)&X[(size_t)(m0 + row) * 512 + k0 + kc * 4];
            As[kc * 4 + 0][row] = v.x;
            As[kc * 4 + 1][row] = v.y;
            As[kc * 4 + 2][row] = v.z;
            As[kc * 4 + 3][row] = v.w;
        }
        // B tile: 64 rows x 16 k (x-part of W: columns [0,512))
        {
            int row = tid >> 2, kc = tid & 3;
            float4 v = *(const float4*)&Wsel[(size_t)(jbase + row) * DH + k0 + kc * 4];
            Bs[kc * 4 + 0][row] = v.x;
            Bs[kc * 4 + 1][row] = v.y;
            Bs[kc * 4 + 2][row] = v.z;
            Bs[kc * 4 + 3][row] = v.w;
        }
        __syncthreads();

#pragma unroll
        for (int k = 0; k < 16; k++) {
            float a[8], bvec[4];
            *(float4*)&a[0] = *(const float4*)&As[k][tm * 4];
            *(float4*)&a[4] = *(const float4*)&As[k][64 + tm * 4];
            *(float4*)&bvec[0] = *(const float4*)&Bs[k][tn * 4];
#pragma unroll
            for (int i = 0; i < 8; i++)
#pragma unroll
                for (int q = 0; q < 4; q++) acc[i][q] += a[i] * bvec[q];
        }
        __syncthreads();
    }

    float bias[4];
#pragma unroll
    for (int q = 0; q < 4; q++) bias[q] = bsel[jbase + tn * 4 + q];

#pragma unroll
    for (int i = 0; i < 8; i++) {
        int m = (i < 4) ? (tm * 4 + i) : (64 + tm * 4 + (i - 4));
        float4 v = make_float4(acc[i][0] + bias[0], acc[i][1] + bias[1],
                               acc[i][2] + bias[2], acc[i][3] + bias[3]);
        *(float4*)&g_zx[(size_t)(m0 + m) * G4 + n0 + tn * 4] = v;
    }
}

// =======================================================================
// Reset kernel: zero barrier counters and h0 (deterministic per replay)
// =======================================================================
__global__ void reset_k()
{
    int tid = threadIdx.x;
    if (tid < NGROUPS) g_cnt[tid] = 0;
    float* p = &g_h[0][0][0];
    for (int i = tid; i < BATCH * HID; i += 256) p[i] = 0.f;
}

// =======================================================================
// Phase 2: persistent sequential LSTM. 128 CTAs (4 groups x 32), 256 thr.
// Each CTA owns 16 hidden units (64 W rows) resident in smem for all t.
// =======================================================================
__global__ __launch_bounds__(256, 1) void lstm_seq(
    const float* __restrict__ Wf, const float* __restrict__ Wi,
    const float* __restrict__ Wg, const float* __restrict__ Wo,
    const float* __restrict__ q_scale, const float* __restrict__ q_bias,
    float* __restrict__ out)
{
    extern __shared__ float sm[];
    float* w_s = sm;                        // [64][KP]
    float* h_s = sm + RPC * KP;             // [16][KP]
    float* red = h_s + BPG * KP;            // [8][1024]
    float* c_s = red + 8 * 1024;            // [256]

    const int tid = threadIdx.x;
    const int cta = blockIdx.x;
    const int grp = cta >> 5;
    const int cig = cta & 31;
    const int b0  = grp * BPG;
    const int j0  = cig * JPC;

    // Load recurrent weights (columns [512,1024) of each W) once.
    for (int idx = tid; idx < RPC * 512; idx += 256) {
        int r = idx >> 9, k = idx & 511;
        int gate = r >> 4, jl_ = r & 15;
        const float* wp = (gate == 0) ? Wf : (gate == 1) ? Wi : (gate == 2) ? Wg : Wo;
        w_s[r * KP + k] = wp[(size_t)(j0 + jl_) * DH + 512 + k];
    }
    c_s[tid] = 0.f;

    const int jl = tid & 15, bl = tid >> 4;
    const int j = j0 + jl, b = b0 + bl;
    const float qs = q_scale[j], qb = q_bias[j];

    const int lane = tid & 31, wrp = tid >> 5;
    const int rL = lane & 7, bL = lane >> 3;
    const int kbase = wrp * 64;
    const int uB = bl >> 2, bLL = bl & 3;

    __syncthreads();

    for (int t = 0; t < T_STEPS; t++) {
        // ---- stage h_t for this group's 16 batches (L2 -> smem) ----
        const float* hsrc = &g_h[t & 1][b0][0];
        for (int i = tid; i < BPG * 128; i += 256) {
            int row = i >> 7, c4 = i & 127;
            float4 v = __ldcg((const float4*)(hsrc + row * 512 + c4 * 4));
            *(float4*)&h_s[row * KP + c4 * 4] = v;
        }
        __syncthreads();

        // ---- GEMM: each warp handles K-chunk of 64, full 16b x 64r tile ----
        float acc[4][8];
#pragma unroll
        for (int u = 0; u < 4; u++)
#pragma unroll
            for (int m = 0; m < 8; m++) acc[u][m] = 0.f;

#pragma unroll 4
        for (int kk = 0; kk < 64; kk += 4) {
            const int k = kbase + kk;
            float4 hf[4], wf[8];
#pragma unroll
            for (int u = 0; u < 4; u++)
                hf[u] = *(const float4*)&h_s[(bL + 4 * u) * KP + k];
#pragma unroll
            for (int m = 0; m < 8; m++)
                wf[m] = *(const float4*)&w_s[(rL + 8 * m) * KP + k];
#pragma unroll
            for (int u = 0; u < 4; u++)
#pragma unroll
                for (int m = 0; m < 8; m++) {
                    acc[u][m] += hf[u].x * wf[m].x;
                    acc[u][m] += hf[u].y * wf[m].y;
                    acc[u][m] += hf[u].z * wf[m].z;
                    acc[u][m] += hf[u].w * wf[m].w;
                }
        }

        // ---- write partials (bank-conflict-free layout) ----
#pragma unroll
        for (int u = 0; u < 4; u++)
#pragma unroll
            for (int m = 0; m < 8; m++)
                red[wrp * 1024 + (u * 8 + m) * 32 + rL * 4 + bL] = acc[u][m];
        __syncthreads();

        // ---- reduce across 8 warps, add Zx, gates, state update ----
        float z[4];
#pragma unroll
        for (int gate = 0; gate < 4; gate++) {
            int r = gate * 16 + jl;
            int idx = (uB * 8 + (r >> 3)) * 32 + (r & 7) * 4 + bLL;
            float s = 0.f;
#pragma unroll
            for (int ww = 0; ww < 8; ww++) s += red[ww * 1024 + idx];
            z[gate] = s + g_zx[((size_t)(t * BATCH + b)) * G4 + gate * 512 + j];
        }

        float sf = 1.f / (1.f + expf(-z[0]));
        float si = 1.f / (1.f + expf(-z[1]));
        float sg = tanhf(z[2]);
        float so = 1.f / (1.f + expf(-z[3]));

        float fg = tanhf(sf * qs + qb);
        float ig = tanhf(si * qs + qb);
        float gg = tanhf(sg * qs + qb);
        float og = tanhf(so * qs + qb);

        float c = fg * c_s[tid] + ig * gg;
        c_s[tid] = c;
        float h = og * tanhf(c);

        g_h[(t + 1) & 1][b][j] = h;
        out[(size_t)t * (BATCH * HID) + b * HID + j] = h;
        if (t == T_STEPS - 1) {
            out[(size_t)T_STEPS * (BATCH * HID) + b * HID + j] = h;                 // hx
            out[(size_t)T_STEPS * (BATCH * HID) + BATCH * HID + b * HID + j] = c;   // cx
        }

        __syncthreads();   // all threads done writing h before arrival

        if (t < T_STEPS - 1) {
            if (tid == 0) {
                __threadfence();
                atomicAdd(&g_cnt[grp], 1u);
                const unsigned target = (unsigned)(t + 1) * CPG;
                while (ld_acq(&g_cnt[grp]) < target) { __nanosleep(32); }
            }
            __syncthreads();
        }
    }
}

// =======================================================================
// Launch
// =======================================================================
extern "C" void kernel_launch(void* const* d_in, const int* in_sizes, int n_in,
                              void* d_out, int out_size)
{
    const float* X  = (const float*)d_in[0];
    const float* Wf = (const float*)d_in[1];
    const float* bf = (const float*)d_in[2];
    const float* Wi = (const float*)d_in[3];
    const float* bi = (const float*)d_in[4];
    const float* Wg = (const float*)d_in[5];
    const float* bg = (const float*)d_in[6];
    const float* Wo = (const float*)d_in[7];
    const float* bo = (const float*)d_in[8];
    const float* qs = (const float*)d_in[9];
    const float* qb = (const float*)d_in[10];
    float* out = (float*)d_out;

    const int smem2 = (RPC * KP + BPG * KP + 8 * 1024 + 256) * (int)sizeof(float);
    cudaFuncSetAttribute(lstm_seq, cudaFuncAttributeMaxDynamicSharedMemorySize, smem2);

    p1_gemm<<<dim3(G4 / 64, (T_STEPS * BATCH) / 128), 256>>>(X, Wf, Wi, Wg, Wo, bf, bi, bg, bo);
    reset_k<<<1, 256>>>();
    lstm_seq<<<NCTA, 256, smem2>>>(Wf, Wi, Wg, Wo, qs, qb, out);
}